// round 8
// baseline (speedup 1.0000x reference)
#include <cuda_runtime.h>

#define HW 65536
#define IMG 256

// Scratch (static __device__ globals, allowed):
static __device__ float g_hidden[(size_t)4 * 384 * HW];
static __device__ float g_qkv[(size_t)4 * 1024 * 384 * 64];

// ---------------------------------------------------------------------------
// Kernel 1: 1x1 conv 64 -> 384 (unchanged; 298us, fma 54.4%)
// ---------------------------------------------------------------------------
__global__ __launch_bounds__(256) void conv1x1_kernel(const float* __restrict__ x,
                                                      const float* __restrict__ w1) {
    extern __shared__ float sm1[];
    float* xs = sm1;            // [64][128]
    float* ws = sm1 + 64 * 128; // [128][64]
    const int t = threadIdx.x;
    const long P0 = (long)blockIdx.x * 128;
    const int b = (int)(P0 >> 16);
    const int hw0 = (int)(P0 & 65535);
    const int o0 = blockIdx.y * 128;

    const float* xb = x + ((long)b * 64) * HW + hw0;
#pragma unroll
    for (int r = 0; r < 8; r++) {
        int idx = t + r * 256;
        int c = idx >> 5;
        int p4 = idx & 31;
        float4 v = *(const float4*)(xb + (long)c * HW + p4 * 4);
        *(float4*)(xs + c * 128 + p4 * 4) = v;
    }
#pragma unroll
    for (int r = 0; r < 8; r++) {
        int idx = t + r * 256;
        int o = idx >> 4;
        int c4 = idx & 15;
        *(float4*)(ws + o * 64 + c4 * 4) =
            *(const float4*)(w1 + (long)(o0 + o) * 64 + c4 * 4);
    }
    __syncthreads();

    const int to = t >> 4, tp = t & 15;
    const int oo = to * 8, pp = tp * 8;
    float acc[8][8];
#pragma unroll
    for (int i = 0; i < 8; i++)
#pragma unroll
        for (int j = 0; j < 8; j++) acc[i][j] = 0.f;

#pragma unroll 4
    for (int k = 0; k < 64; k++) {
        float av[8];
#pragma unroll
        for (int i = 0; i < 8; i++) av[i] = ws[(oo + i) * 64 + k];
        float4 b0 = *(const float4*)(xs + k * 128 + pp);
        float4 b1 = *(const float4*)(xs + k * 128 + pp + 4);
        float bv[8] = {b0.x, b0.y, b0.z, b0.w, b1.x, b1.y, b1.z, b1.w};
#pragma unroll
        for (int i = 0; i < 8; i++)
#pragma unroll
            for (int j = 0; j < 8; j++) acc[i][j] += av[i] * bv[j];
    }

    float* hb = g_hidden + ((long)b * 384 + o0) * HW + hw0;
#pragma unroll
    for (int i = 0; i < 8; i++) {
        float4 v0 = make_float4(acc[i][0], acc[i][1], acc[i][2], acc[i][3]);
        float4 v1 = make_float4(acc[i][4], acc[i][5], acc[i][6], acc[i][7]);
        *(float4*)(hb + (long)(oo + i) * HW + pp) = v0;
        *(float4*)(hb + (long)(oo + i) * HW + pp + 4) = v1;
    }
}

// ---------------------------------------------------------------------------
// Kernel 2: depthwise 3x3 (unchanged), writes patched qkv layout.
// ---------------------------------------------------------------------------
__global__ __launch_bounds__(256) void dw3x3_kernel(const float* __restrict__ wdw) {
    __shared__ float smh[66 * 68];
    const int t = threadIdx.x;
    const int tix = blockIdx.x;
    const int ch = blockIdx.y;
    const int b = blockIdx.z;
    const int ty = tix >> 2, tx = tix & 3;
    const int y0 = ty * 64, x0 = tx * 64;

    const float* src = g_hidden + (long)(b * 384 + ch) * HW;
    for (int l = t; l < 66 * 66; l += 256) {
        int r = l / 66, c = l - r * 66;
        int y = y0 + r - 1, x = x0 + c - 1;
        float v = 0.f;
        if ((unsigned)y < 256u && (unsigned)x < 256u) v = src[y * IMG + x];
        smh[r * 68 + c] = v;
    }
    float w[9];
#pragma unroll
    for (int i = 0; i < 9; i++) w[i] = __ldg(wdw + ch * 9 + i);
    __syncthreads();

#pragma unroll 4
    for (int i = 0; i < 16; i++) {
        int L = t + i * 256;
        int p = L >> 6, inner = L & 63;
        int tpy = p >> 3, tpx = p & 7;
        int iy = inner >> 3, ix = inner & 7;
        int y = tpy * 8 + iy, x = tpx * 8 + ix;
        float acc = 0.f;
#pragma unroll
        for (int ky = 0; ky < 3; ky++)
#pragma unroll
            for (int kx = 0; kx < 3; kx++)
                acc += smh[(y + ky) * 68 + (x + kx)] * w[ky * 3 + kx];
        int pg = (ty * 8 + tpy) * 32 + (tx * 8 + tpx);
        g_qkv[((long)(b * 1024 + pg) * 384 + ch) * 64 + inner] = acc;
    }
}

// ---------------------------------------------------------------------------
// Kernel 3: per-patch attention, v3.
//   bufQ  @0      [128][68]  (8704)  q -> conv (in place) -> gated (in place)
//   bufK  @8704   [128][72]  (9216)  k, stride-9 rows (dead after phase 2)
//   psum  @17920  [4][64]
//   psq   @18176  [4][64]
//   mu_s  @18432  [64]
//   rs_s  @18496  [64]
// total = 18560 floats = 74240 B -> 3 CTAs/SM (222.7KB of 228)
// ---------------------------------------------------------------------------
#define SQ 68
#define S_BUFK 8704
#define S_PSUM 17920
#define S_PSQ 18176
#define S_MU 18432
#define S_RS 18496
#define SMEM2_FLOATS 18560

__global__ __launch_bounds__(256, 3) void fsas2_kernel(const float* __restrict__ w_out,
                                                       const float* __restrict__ lnw,
                                                       const float* __restrict__ lnb,
                                                       float* __restrict__ out) {
    extern __shared__ float sm[];
    float* bufQ = sm;
    float* bufK = sm + S_BUFK;
    float* psum = sm + S_PSUM;
    float* psq = sm + S_PSQ;
    float* mu_s = sm + S_MU;
    float* rs_s = sm + S_RS;

    const int t = threadIdx.x;
    const int pid = blockIdx.x;
    const int b = pid >> 10;
    const int patch = pid & 1023;
    const int ph = patch >> 5;
    const int pw = patch & 31;
    const int y0 = ph * 8, x0 = pw * 8;
    const int lane = t >> 6;       // 0..3
    const int pix = t & 63;

    const float* base = g_qkv + (long)pid * 384 * 64;

    // ---- Phase 1: prefetch v to registers; load q (stride-68), k (stride-9) ----
    float4 vreg[8];
#pragma unroll
    for (int r = 0; r < 8; r++)
        vreg[r] = ((const float4*)base)[4096 + r * 256 + t];   // v region

#pragma unroll
    for (int r = 0; r < 8; r++) {
        int idx = t + r * 256;               // 2048 f4 = 128 ch x 16 f4
        float4 v = ((const float4*)base)[idx];
        int c = idx >> 4;
        int word = (idx & 15) * 4;
        *(float4*)(bufQ + c * SQ + word) = v;
    }
#pragma unroll
    for (int r = 0; r < 8; r++) {
        int idx = t + r * 256;
        float4 v = ((const float4*)(base + 8192))[idx];
        int c = idx >> 4;
        int word = (idx & 15) * 4;
        int row = word >> 3, col = word & 7;
        float* dk = bufK + c * 72 + row * 9 + col;
        dk[0] = v.x; dk[1] = v.y; dk[2] = v.z; dk[3] = v.w;
    }
    __syncthreads();

    // ---- Phase 2: 8x8 circular conv; warp owns 16-ch band; in place in bufQ ----
    {
        const int w = t >> 5;      // warp 0..7
        const int ln = t & 31;
        const int aa = ln & 7;
        const int csub = ln >> 3;  // 0..3
#pragma unroll 1
        for (int r = 0; r < 4; r++) {
            int c = w * 16 + r * 4 + csub;
            const float* bq = bufQ + c * SQ;
            const float* bk = bufK + c * 72;
            float acc[8];
#pragma unroll
            for (int bb = 0; bb < 8; bb++) acc[bb] = 0.f;
#pragma unroll
            for (int i = 0; i < 8; i++) {
                float4 q0 = *(const float4*)(bq + i * 8);
                float4 q1 = *(const float4*)(bq + i * 8 + 4);
                float qr[8] = {q0.x, q0.y, q0.z, q0.w, q1.x, q1.y, q1.z, q1.w};
                int ka = (aa - i) & 7;
                const float* kr = bk + ka * 9;
                float kk[8];
#pragma unroll
                for (int m = 0; m < 8; m++) kk[m] = kr[m];
#pragma unroll
                for (int j = 0; j < 8; j++)
#pragma unroll
                    for (int bb = 0; bb < 8; bb++) acc[bb] += qr[j] * kk[(bb - j) & 7];
            }
            __syncwarp();
            float* co = bufQ + c * SQ + aa * 8;
            *(float4*)(co) = make_float4(acc[0], acc[1], acc[2], acc[3]);
            *(float4*)(co + 4) = make_float4(acc[4], acc[5], acc[6], acc[7]);
        }
    }
    __syncthreads();

    // ---- Phase 3a: LN partial sums over 128 channels ----
    {
        float s = 0.f, s2 = 0.f;
#pragma unroll 1
        for (int cb = 0; cb < 32; cb++) {
            float v = bufQ[(cb * 4 + lane) * SQ + pix];
            s += v;
            s2 += v * v;
        }
        psum[lane * 64 + pix] = s;
        psq[lane * 64 + pix] = s2;
    }
    __syncthreads();

    // ---- Phase 3a': per-pixel mu/rstd (64 threads) ----
    if (t < 64) {
        float mu = (psum[t] + psum[64 + t] + psum[128 + t] + psum[192 + t]) *
                   (1.f / 128.f);
        float ex2 = (psq[t] + psq[64 + t] + psq[128 + t] + psq[192 + t]) *
                    (1.f / 128.f);
        mu_s[t] = mu;
        rs_s[t] = rsqrtf(ex2 - mu * mu + 1e-5f);
    }
    __syncthreads();

    // ---- Phase 3b: normalize + gate by v, in place in bufQ ([c][pix] layout) ----
#pragma unroll
    for (int r = 0; r < 8; r++) {
        int task = r * 256 + t;              // 2048 tasks = 128 ch x 16 pix4
        int c = task >> 4;
        int p0 = (task & 15) * 4;
        float* g = bufQ + c * SQ + p0;
        float4 cv = *(const float4*)g;
        float lw = __ldg(lnw + c), lb = __ldg(lnb + c);
        float4 vv = vreg[r];
        float4 o4;
        o4.x = ((cv.x - mu_s[p0 + 0]) * rs_s[p0 + 0] * lw + lb) * vv.x;
        o4.y = ((cv.y - mu_s[p0 + 1]) * rs_s[p0 + 1] * lw + lb) * vv.y;
        o4.z = ((cv.z - mu_s[p0 + 2]) * rs_s[p0 + 2] * lw + lb) * vv.z;
        o4.w = ((cv.w - mu_s[p0 + 3]) * rs_s[p0 + 3] * lw + lb) * vv.w;
        *(float4*)g = o4;
    }
    __syncthreads();

    // ---- Phase 4: projection 128 -> 64 from [c][pix], direct global store ----
    {
        int o = t >> 2;                 // 0..63 output channel
        int pb = t & 3;                 // pixel block: pix 16*pb .. 16*pb+15
        float acc[16];
#pragma unroll
        for (int i = 0; i < 16; i++) acc[i] = 0.f;
        const float4* wrow = (const float4*)(w_out) + o * 32;
#pragma unroll 2
        for (int cq = 0; cq < 32; cq++) {
            float4 w4 = __ldg(wrow + cq);
            float wv[4] = {w4.x, w4.y, w4.z, w4.w};
#pragma unroll
            for (int i = 0; i < 4; i++) {
                const float* g = bufQ + (cq * 4 + i) * SQ + pb * 16;
                float4 g0 = *(const float4*)(g);
                float4 g1 = *(const float4*)(g + 4);
                float4 g2 = *(const float4*)(g + 8);
                float4 g3 = *(const float4*)(g + 12);
                acc[0] += wv[i] * g0.x;  acc[1] += wv[i] * g0.y;
                acc[2] += wv[i] * g0.z;  acc[3] += wv[i] * g0.w;
                acc[4] += wv[i] * g1.x;  acc[5] += wv[i] * g1.y;
                acc[6] += wv[i] * g1.z;  acc[7] += wv[i] * g1.w;
                acc[8] += wv[i] * g2.x;  acc[9] += wv[i] * g2.y;
                acc[10] += wv[i] * g2.z; acc[11] += wv[i] * g2.w;
                acc[12] += wv[i] * g3.x; acc[13] += wv[i] * g3.y;
                acc[14] += wv[i] * g3.z; acc[15] += wv[i] * g3.w;
            }
        }
        // pix 16*pb..16*pb+15 = patch rows 2*pb, 2*pb+1 (8 cols each)
        float* ob = out + ((long)(b * 64 + o) * IMG + y0 + pb * 2) * IMG + x0;
        *(float4*)(ob) = make_float4(acc[0], acc[1], acc[2], acc[3]);
        *(float4*)(ob + 4) = make_float4(acc[4], acc[5], acc[6], acc[7]);
        *(float4*)(ob + IMG) = make_float4(acc[8], acc[9], acc[10], acc[11]);
        *(float4*)(ob + IMG + 4) = make_float4(acc[12], acc[13], acc[14], acc[15]);
    }
}

// ---------------------------------------------------------------------------
extern "C" void kernel_launch(void* const* d_in, const int* in_sizes, int n_in,
                              void* d_out, int out_size) {
    const float* x = (const float*)d_in[0];
    const float* w1 = (const float*)d_in[1];
    const float* wdw = (const float*)d_in[2];
    const float* wout = (const float*)d_in[3];
    const float* lnw = (const float*)d_in[4];
    const float* lnb = (const float*)d_in[5];
    float* out = (float*)d_out;

    cudaFuncSetAttribute(conv1x1_kernel, cudaFuncAttributeMaxDynamicSharedMemorySize,
                         64 * 128 * 4 + 128 * 64 * 4);
    cudaFuncSetAttribute(fsas2_kernel, cudaFuncAttributeMaxDynamicSharedMemorySize,
                         SMEM2_FLOATS * 4);

    conv1x1_kernel<<<dim3(2048, 3, 1), 256, 64 * 128 * 4 + 128 * 64 * 4>>>(x, w1);
    dw3x3_kernel<<<dim3(16, 384, 4), 256>>>(wdw);
    fsas2_kernel<<<4096, 256, SMEM2_FLOATS * 4>>>(wout, lnw, lnb, out);
}

// round 10
// speedup vs baseline: 1.1465x; 1.1465x over previous
#include <cuda_runtime.h>

#define HW 65536
#define IMG 256

typedef unsigned long long u64;

static __device__ float g_hidden[(size_t)4 * 384 * HW];
static __device__ float g_qkv[(size_t)4 * 1024 * 384 * 64];

__device__ __forceinline__ u64 ffma2(u64 a, u64 b, u64 c) {
    u64 d;
    asm("fma.rn.f32x2 %0, %1, %2, %3;" : "=l"(d) : "l"(a), "l"(b), "l"(c));
    return d;
}
__device__ __forceinline__ u64 splat2(float a) {
    u64 r;
    asm("mov.b64 %0, {%1, %1};" : "=l"(r) : "f"(a));
    return r;
}
__device__ __forceinline__ float2 unpk(u64 v) {
    float lo, hi;
    asm("mov.b64 {%0, %1}, %2;" : "=f"(lo), "=f"(hi) : "l"(v));
    return make_float2(lo, hi);
}

// ---------------------------------------------------------------------------
// Kernel 1: 1x1 conv 64 -> 384, f32x2 version.
// smem: xs [64][128] floats @0; wsd [128][64] u64 (splatted weights) @8192fl.
// 256 threads, each computes 8 o x 8 px (as 8 x 4 f32x2 pairs).
// ---------------------------------------------------------------------------
#define C1_SMEM_BYTES (8192 * 4 + 8192 * 8)

__global__ __launch_bounds__(256) void conv1x1_kernel(const float* __restrict__ x,
                                                      const float* __restrict__ w1) {
    extern __shared__ float sm1[];
    float* xs = sm1;                               // [64][128]
    u64* wsd = (u64*)(sm1 + 8192);                 // [128][64] splatted
    const int t = threadIdx.x;
    const long P0 = (long)blockIdx.x * 128;
    const int b = (int)(P0 >> 16);
    const int hw0 = (int)(P0 & 65535);
    const int o0 = blockIdx.y * 128;

    const float* xb = x + ((long)b * 64) * HW + hw0;
#pragma unroll
    for (int r = 0; r < 8; r++) {
        int idx = t + r * 256;        // 2048 f4 = 64 rows x 32 f4
        int c = idx >> 5;
        int p4 = idx & 31;
        float4 v = *(const float4*)(xb + (long)c * HW + p4 * 4);
        *(float4*)(xs + c * 128 + p4 * 4) = v;
    }
#pragma unroll
    for (int r = 0; r < 8; r++) {
        int idx = t + r * 256;        // 2048 f4 = 128 rows x 16 f4
        int o = idx >> 4;
        int c4 = idx & 15;
        float4 w = *(const float4*)(w1 + (long)(o0 + o) * 64 + c4 * 4);
        u64* d = wsd + o * 64 + c4 * 4;
        d[0] = splat2(w.x); d[1] = splat2(w.y); d[2] = splat2(w.z); d[3] = splat2(w.w);
    }
    __syncthreads();

    const int to = t >> 4, tp = t & 15;
    const int oo = to * 8, pp = tp * 8;
    u64 acc2[8][4];
    const u64 z = splat2(0.f);
#pragma unroll
    for (int i = 0; i < 8; i++)
#pragma unroll
        for (int j = 0; j < 4; j++) acc2[i][j] = z;

#pragma unroll 4
    for (int k = 0; k < 64; k++) {
        u64 av2[8];
#pragma unroll
        for (int i = 0; i < 8; i++) av2[i] = wsd[(oo + i) * 64 + k];
        ulonglong2 p0 = *(const ulonglong2*)(xs + k * 128 + pp);
        ulonglong2 p1 = *(const ulonglong2*)(xs + k * 128 + pp + 4);
        u64 bv[4] = {p0.x, p0.y, p1.x, p1.y};
#pragma unroll
        for (int i = 0; i < 8; i++)
#pragma unroll
            for (int j = 0; j < 4; j++) acc2[i][j] = ffma2(av2[i], bv[j], acc2[i][j]);
    }

    float* hb = g_hidden + ((long)b * 384 + o0) * HW + hw0;
#pragma unroll
    for (int i = 0; i < 8; i++) {
        ulonglong2 s0, s1;
        s0.x = acc2[i][0]; s0.y = acc2[i][1];
        s1.x = acc2[i][2]; s1.y = acc2[i][3];
        *(ulonglong2*)(hb + (long)(oo + i) * HW + pp) = s0;
        *(ulonglong2*)(hb + (long)(oo + i) * HW + pp + 4) = s1;
    }
}

// ---------------------------------------------------------------------------
// Kernel 2: depthwise 3x3 (unchanged), writes patched qkv layout.
// ---------------------------------------------------------------------------
__global__ __launch_bounds__(256) void dw3x3_kernel(const float* __restrict__ wdw) {
    __shared__ float smh[66 * 68];
    const int t = threadIdx.x;
    const int tix = blockIdx.x;
    const int ch = blockIdx.y;
    const int b = blockIdx.z;
    const int ty = tix >> 2, tx = tix & 3;
    const int y0 = ty * 64, x0 = tx * 64;

    const float* src = g_hidden + (long)(b * 384 + ch) * HW;
    for (int l = t; l < 66 * 66; l += 256) {
        int r = l / 66, c = l - r * 66;
        int y = y0 + r - 1, x = x0 + c - 1;
        float v = 0.f;
        if ((unsigned)y < 256u && (unsigned)x < 256u) v = src[y * IMG + x];
        smh[r * 68 + c] = v;
    }
    float w[9];
#pragma unroll
    for (int i = 0; i < 9; i++) w[i] = __ldg(wdw + ch * 9 + i);
    __syncthreads();

#pragma unroll 4
    for (int i = 0; i < 16; i++) {
        int L = t + i * 256;
        int p = L >> 6, inner = L & 63;
        int tpy = p >> 3, tpx = p & 7;
        int iy = inner >> 3, ix = inner & 7;
        int y = tpy * 8 + iy, x = tpx * 8 + ix;
        float acc = 0.f;
#pragma unroll
        for (int ky = 0; ky < 3; ky++)
#pragma unroll
            for (int kx = 0; kx < 3; kx++)
                acc += smh[(y + ky) * 68 + (x + kx)] * w[ky * 3 + kx];
        int pg = (ty * 8 + tpy) * 32 + (tx * 8 + tpx);
        g_qkv[((long)(b * 1024 + pg) * 384 + ch) * 64 + inner] = acc;
    }
}

// ---------------------------------------------------------------------------
// Kernel 3: per-patch attention — exact 1022us structure; phase 4 uses
// reduction-paired f32x2 (w and gatedT consumed as natural 64-bit pairs).
//   bufQ  @0      [128][68]  q -> conv (in place)
//   bufK  @8704   [128][72]  k stride-9 rows; becomes gatedT [64][132] overlay
//   projbuf @0    [64][68]   overlay (bufQ dead)
//   psum @17920, psq @18176  [4][64]
// total = 18432 floats = 73728 B -> 3 CTAs/SM
// ---------------------------------------------------------------------------
#define SQ 68
#define S_BUFK 8704
#define S_PSUM 17920
#define S_PSQ 18176
#define SMEM2_FLOATS 18432

__global__ __launch_bounds__(256, 3) void fsas2_kernel(const float* __restrict__ w_out,
                                                       const float* __restrict__ lnw,
                                                       const float* __restrict__ lnb,
                                                       float* __restrict__ out) {
    extern __shared__ float sm[];
    float* bufQ = sm;
    float* bufK = sm + S_BUFK;
    float* gatedT = bufK;
    float* projbuf = sm;
    float* psum = sm + S_PSUM;
    float* psq = sm + S_PSQ;

    const int t = threadIdx.x;
    const int pid = blockIdx.x;
    const int b = pid >> 10;
    const int patch = pid & 1023;
    const int ph = patch >> 5;
    const int pw = patch & 31;
    const int y0 = ph * 8, x0 = pw * 8;
    const int lane = t >> 6;
    const int pix = t & 63;

    const float* base = g_qkv + (long)pid * 384 * 64;

    // ---- Phase 1: load q (stride-68 rows) and k (stride-9 rows) ----
#pragma unroll
    for (int r = 0; r < 8; r++) {
        int idx = t + r * 256;
        float4 v = ((const float4*)base)[idx];
        int c = idx >> 4;
        int word = (idx & 15) * 4;
        *(float4*)(bufQ + c * SQ + word) = v;
    }
#pragma unroll
    for (int r = 0; r < 8; r++) {
        int idx = t + r * 256;
        float4 v = ((const float4*)(base + 8192))[idx];
        int c = idx >> 4;
        int word = (idx & 15) * 4;
        int row = word >> 3, col = word & 7;
        float* dk = bufK + c * 72 + row * 9 + col;
        dk[0] = v.x; dk[1] = v.y; dk[2] = v.z; dk[3] = v.w;
    }
    __syncthreads();

    // ---- Phase 2: 8x8 circular conv; warp owns 16-ch band; in place ----
    {
        const int w = t >> 5;
        const int ln = t & 31;
        const int aa = ln & 7;
        const int csub = ln >> 3;
#pragma unroll 1
        for (int r = 0; r < 4; r++) {
            int c = w * 16 + r * 4 + csub;
            const float* bq = bufQ + c * SQ;
            const float* bk = bufK + c * 72;
            float acc[8];
#pragma unroll
            for (int bb = 0; bb < 8; bb++) acc[bb] = 0.f;
#pragma unroll
            for (int i = 0; i < 8; i++) {
                float4 q0 = *(const float4*)(bq + i * 8);
                float4 q1 = *(const float4*)(bq + i * 8 + 4);
                float qr[8] = {q0.x, q0.y, q0.z, q0.w, q1.x, q1.y, q1.z, q1.w};
                int ka = (aa - i) & 7;
                const float* kr = bk + ka * 9;
                float kk[8];
#pragma unroll
                for (int m = 0; m < 8; m++) kk[m] = kr[m];
#pragma unroll
                for (int j = 0; j < 8; j++)
#pragma unroll
                    for (int bb = 0; bb < 8; bb++) acc[bb] += qr[j] * kk[(bb - j) & 7];
            }
            __syncwarp();
            float* co = bufQ + c * SQ + aa * 8;
            *(float4*)(co) = make_float4(acc[0], acc[1], acc[2], acc[3]);
            *(float4*)(co + 4) = make_float4(acc[4], acc[5], acc[6], acc[7]);
        }
    }
    __syncthreads();

    // ---- Phase 3a: LN partial sums over 128 channels ----
    {
        float s = 0.f, s2 = 0.f;
#pragma unroll 1
        for (int cb = 0; cb < 32; cb++) {
            float v = bufQ[(cb * 4 + lane) * SQ + pix];
            s += v;
            s2 += v * v;
        }
        psum[lane * 64 + pix] = s;
        psq[lane * 64 + pix] = s2;
    }
    __syncthreads();

    // ---- Phase 3b: normalize, gate by v (from global), write gatedT ----
    {
        float mu = (psum[pix] + psum[64 + pix] + psum[128 + pix] + psum[192 + pix]) *
                   (1.f / 128.f);
        float ex2 = (psq[pix] + psq[64 + pix] + psq[128 + pix] + psq[192 + pix]) *
                    (1.f / 128.f);
        float var = ex2 - mu * mu;
        float rstd = rsqrtf(var + 1e-5f);
        const float* vsrc = base + 256 * 64;
#pragma unroll 8
        for (int cb = 0; cb < 32; cb++) {
            int c = cb * 4 + lane;
            float vv = __ldg(vsrc + c * 64 + pix);
            float g = (bufQ[c * SQ + pix] - mu) * rstd * __ldg(lnw + c) + __ldg(lnb + c);
            gatedT[pix * 132 + c] = g * vv;
        }
    }
    __syncthreads();

    // ---- Phase 4: projection 128 -> 64, f32x2 reduction pairs ----
    {
        int o = t >> 2;       // 0..63
        int pl = t & 3;       // pixel interleave lane
        u64 acc2[16];
        const u64 z = splat2(0.f);
#pragma unroll
        for (int pp2 = 0; pp2 < 16; pp2++) acc2[pp2] = z;
        const ulonglong2* wrow = (const ulonglong2*)(w_out + o * 128);
#pragma unroll 1
        for (int cq = 0; cq < 32; cq++) {
            ulonglong2 w2 = __ldg(wrow + cq);
#pragma unroll
            for (int pp2 = 0; pp2 < 16; pp2++) {
                int p = pp2 * 4 + pl;
                ulonglong2 g2 = *(const ulonglong2*)(gatedT + p * 132 + cq * 4);
                acc2[pp2] = ffma2(w2.x, g2.x, acc2[pp2]);
                acc2[pp2] = ffma2(w2.y, g2.y, acc2[pp2]);
            }
        }
#pragma unroll
        for (int pp2 = 0; pp2 < 16; pp2++) {
            float2 r = unpk(acc2[pp2]);
            projbuf[o * 68 + pp2 * 4 + pl] = r.x + r.y;
        }
    }
    __syncthreads();

    // ---- Phase 5: coalesced writeout ----
    {
        int o2 = t >> 2;
        int part = t & 3;
        float* ob = out + ((long)(b * 64 + o2) * IMG + y0) * IMG + x0;
#pragma unroll
        for (int ry = 0; ry < 2; ry++) {
            int y = part * 2 + ry;
            float4 v0 = *(const float4*)(projbuf + o2 * 68 + y * 8);
            float4 v1 = *(const float4*)(projbuf + o2 * 68 + y * 8 + 4);
            *(float4*)(ob + y * IMG) = v0;
            *(float4*)(ob + y * IMG + 4) = v1;
        }
    }
}

// ---------------------------------------------------------------------------
extern "C" void kernel_launch(void* const* d_in, const int* in_sizes, int n_in,
                              void* d_out, int out_size) {
    const float* x = (const float*)d_in[0];
    const float* w1 = (const float*)d_in[1];
    const float* wdw = (const float*)d_in[2];
    const float* wout = (const float*)d_in[3];
    const float* lnw = (const float*)d_in[4];
    const float* lnb = (const float*)d_in[5];
    float* out = (float*)d_out;

    cudaFuncSetAttribute(conv1x1_kernel, cudaFuncAttributeMaxDynamicSharedMemorySize,
                         C1_SMEM_BYTES);
    cudaFuncSetAttribute(fsas2_kernel, cudaFuncAttributeMaxDynamicSharedMemorySize,
                         SMEM2_FLOATS * 4);

    conv1x1_kernel<<<dim3(2048, 3, 1), 256, C1_SMEM_BYTES>>>(x, w1);
    dw3x3_kernel<<<dim3(16, 384, 4), 256>>>(wdw);
    fsas2_kernel<<<4096, 256, SMEM2_FLOATS * 4>>>(wout, lnw, lnb, out);
}

// round 11
// speedup vs baseline: 1.1906x; 1.0385x over previous
#include <cuda_runtime.h>

#define HW 65536
#define IMG 256

typedef unsigned long long u64;

static __device__ float g_hidden[(size_t)4 * 384 * HW];
static __device__ float g_qkv[(size_t)4 * 1024 * 384 * 64];

__device__ __forceinline__ u64 ffma2(u64 a, u64 b, u64 c) {
    u64 d;
    asm("fma.rn.f32x2 %0, %1, %2, %3;" : "=l"(d) : "l"(a), "l"(b), "l"(c));
    return d;
}
__device__ __forceinline__ u64 pack2(float lo, float hi) {
    u64 r;
    asm("mov.b64 %0, {%1, %2};" : "=l"(r) : "f"(lo), "f"(hi));
    return r;
}
__device__ __forceinline__ u64 splat2(float a) {
    u64 r;
    asm("mov.b64 %0, {%1, %1};" : "=l"(r) : "f"(a));
    return r;
}
__device__ __forceinline__ float2 unpk(u64 v) {
    float lo, hi;
    asm("mov.b64 {%0, %1}, %2;" : "=f"(lo), "=f"(hi) : "l"(v));
    return make_float2(lo, hi);
}

// ---------------------------------------------------------------------------
// Kernel 1: 1x1 conv 64 -> 384, scalar FFMA (proven 298us, issue 62%).
// ---------------------------------------------------------------------------
#define C1_SMEM_BYTES ((64 * 128 + 128 * 64) * 4)

__global__ __launch_bounds__(256) void conv1x1_kernel(const float* __restrict__ x,
                                                      const float* __restrict__ w1) {
    extern __shared__ float sm1[];
    float* xs = sm1;            // [64][128]
    float* ws = sm1 + 64 * 128; // [128][64]
    const int t = threadIdx.x;
    const long P0 = (long)blockIdx.x * 128;
    const int b = (int)(P0 >> 16);
    const int hw0 = (int)(P0 & 65535);
    const int o0 = blockIdx.y * 128;

    const float* xb = x + ((long)b * 64) * HW + hw0;
#pragma unroll
    for (int r = 0; r < 8; r++) {
        int idx = t + r * 256;
        int c = idx >> 5;
        int p4 = idx & 31;
        float4 v = *(const float4*)(xb + (long)c * HW + p4 * 4);
        *(float4*)(xs + c * 128 + p4 * 4) = v;
    }
#pragma unroll
    for (int r = 0; r < 8; r++) {
        int idx = t + r * 256;
        int o = idx >> 4;
        int c4 = idx & 15;
        *(float4*)(ws + o * 64 + c4 * 4) =
            *(const float4*)(w1 + (long)(o0 + o) * 64 + c4 * 4);
    }
    __syncthreads();

    const int to = t >> 4, tp = t & 15;
    const int oo = to * 8, pp = tp * 8;
    float acc[8][8];
#pragma unroll
    for (int i = 0; i < 8; i++)
#pragma unroll
        for (int j = 0; j < 8; j++) acc[i][j] = 0.f;

#pragma unroll 4
    for (int k = 0; k < 64; k++) {
        float av[8];
#pragma unroll
        for (int i = 0; i < 8; i++) av[i] = ws[(oo + i) * 64 + k];
        float4 b0 = *(const float4*)(xs + k * 128 + pp);
        float4 b1 = *(const float4*)(xs + k * 128 + pp + 4);
        float bv[8] = {b0.x, b0.y, b0.z, b0.w, b1.x, b1.y, b1.z, b1.w};
#pragma unroll
        for (int i = 0; i < 8; i++)
#pragma unroll
            for (int j = 0; j < 8; j++) acc[i][j] += av[i] * bv[j];
    }

    float* hb = g_hidden + ((long)b * 384 + o0) * HW + hw0;
#pragma unroll
    for (int i = 0; i < 8; i++) {
        float4 v0 = make_float4(acc[i][0], acc[i][1], acc[i][2], acc[i][3]);
        float4 v1 = make_float4(acc[i][4], acc[i][5], acc[i][6], acc[i][7]);
        *(float4*)(hb + (long)(oo + i) * HW + pp) = v0;
        *(float4*)(hb + (long)(oo + i) * HW + pp + 4) = v1;
    }
}

// ---------------------------------------------------------------------------
// Kernel 2: depthwise 3x3 (unchanged), writes patched qkv layout.
// ---------------------------------------------------------------------------
__global__ __launch_bounds__(256) void dw3x3_kernel(const float* __restrict__ wdw) {
    __shared__ float smh[66 * 68];
    const int t = threadIdx.x;
    const int tix = blockIdx.x;
    const int ch = blockIdx.y;
    const int b = blockIdx.z;
    const int ty = tix >> 2, tx = tix & 3;
    const int y0 = ty * 64, x0 = tx * 64;

    const float* src = g_hidden + (long)(b * 384 + ch) * HW;
    for (int l = t; l < 66 * 66; l += 256) {
        int r = l / 66, c = l - r * 66;
        int y = y0 + r - 1, x = x0 + c - 1;
        float v = 0.f;
        if ((unsigned)y < 256u && (unsigned)x < 256u) v = src[y * IMG + x];
        smh[r * 68 + c] = v;
    }
    float w[9];
#pragma unroll
    for (int i = 0; i < 9; i++) w[i] = __ldg(wdw + ch * 9 + i);
    __syncthreads();

#pragma unroll 4
    for (int i = 0; i < 16; i++) {
        int L = t + i * 256;
        int p = L >> 6, inner = L & 63;
        int tpy = p >> 3, tpx = p & 7;
        int iy = inner >> 3, ix = inner & 7;
        int y = tpy * 8 + iy, x = tpx * 8 + ix;
        float acc = 0.f;
#pragma unroll
        for (int ky = 0; ky < 3; ky++)
#pragma unroll
            for (int kx = 0; kx < 3; kx++)
                acc += smh[(y + ky) * 68 + (x + kx)] * w[ky * 3 + kx];
        int pg = (ty * 8 + tpy) * 32 + (tx * 8 + tpx);
        g_qkv[((long)(b * 1024 + pg) * 384 + ch) * 64 + inner] = acc;
    }
}

// ---------------------------------------------------------------------------
// Kernel 3: per-patch attention (1022us structure).
// Phase 2 and phase 4 use reduction-paired f32x2.
//   bufQ  @0      [128][68]  q -> conv (in place)
//   bufK  @8704   [128][72]  k stride-9 rows; becomes gatedT [64][132] overlay
//   projbuf @0    [64][68]   overlay (bufQ dead)
//   psum @17920, psq @18176  [4][64]
// total = 18432 floats = 73728 B -> 3 CTAs/SM
// ---------------------------------------------------------------------------
#define SQ 68
#define S_BUFK 8704
#define S_PSUM 17920
#define S_PSQ 18176
#define SMEM2_FLOATS 18432

__global__ __launch_bounds__(256, 3) void fsas2_kernel(const float* __restrict__ w_out,
                                                       const float* __restrict__ lnw,
                                                       const float* __restrict__ lnb,
                                                       float* __restrict__ out) {
    extern __shared__ float sm[];
    float* bufQ = sm;
    float* bufK = sm + S_BUFK;
    float* gatedT = bufK;
    float* projbuf = sm;
    float* psum = sm + S_PSUM;
    float* psq = sm + S_PSQ;

    const int t = threadIdx.x;
    const int pid = blockIdx.x;
    const int b = pid >> 10;
    const int patch = pid & 1023;
    const int ph = patch >> 5;
    const int pw = patch & 31;
    const int y0 = ph * 8, x0 = pw * 8;
    const int lane = t >> 6;
    const int pix = t & 63;

    const float* base = g_qkv + (long)pid * 384 * 64;

    // ---- Phase 1: load q (stride-68 rows) and k (stride-9 rows) ----
#pragma unroll
    for (int r = 0; r < 8; r++) {
        int idx = t + r * 256;
        float4 v = ((const float4*)base)[idx];
        int c = idx >> 4;
        int word = (idx & 15) * 4;
        *(float4*)(bufQ + c * SQ + word) = v;
    }
#pragma unroll
    for (int r = 0; r < 8; r++) {
        int idx = t + r * 256;
        float4 v = ((const float4*)(base + 8192))[idx];
        int c = idx >> 4;
        int word = (idx & 15) * 4;
        int row = word >> 3, col = word & 7;
        float* dk = bufK + c * 72 + row * 9 + col;
        dk[0] = v.x; dk[1] = v.y; dk[2] = v.z; dk[3] = v.w;
    }
    __syncthreads();

    // ---- Phase 2: 8x8 circular conv, f32x2 reduction-paired over j.
    //      acc2[bb] accumulates (qr[j]*kk[(bb-j)], qr[j+1]*kk[(bb-j-1)]);
    //      q pairs are free (ulonglong2 LDS); kkq[r]=(kk[r],kk[(r-1)&7]).
    {
        const int w = t >> 5;
        const int ln = t & 31;
        const int aa = ln & 7;
        const int csub = ln >> 3;
#pragma unroll 1
        for (int r = 0; r < 4; r++) {
            int c = w * 16 + r * 4 + csub;
            const float* bq = bufQ + c * SQ;
            const float* bk = bufK + c * 72;
            u64 acc2[8];
            const u64 z = splat2(0.f);
#pragma unroll
            for (int bb = 0; bb < 8; bb++) acc2[bb] = z;
#pragma unroll
            for (int i = 0; i < 8; i++) {
                ulonglong2 qp0 = *(const ulonglong2*)(bq + i * 8);      // (q0q1, q2q3)
                ulonglong2 qp1 = *(const ulonglong2*)(bq + i * 8 + 4);  // (q4q5, q6q7)
                u64 qp[4] = {qp0.x, qp0.y, qp1.x, qp1.y};
                int ka = (aa - i) & 7;
                const float* kr = bk + ka * 9;
                float kk[8];
#pragma unroll
                for (int m = 0; m < 8; m++) kk[m] = kr[m];
                u64 kkq[8];
#pragma unroll
                for (int m = 0; m < 8; m++) kkq[m] = pack2(kk[m], kk[(m - 1) & 7]);
#pragma unroll
                for (int jp = 0; jp < 4; jp++)
#pragma unroll
                    for (int bb = 0; bb < 8; bb++)
                        acc2[bb] = ffma2(qp[jp], kkq[(bb - 2 * jp) & 7], acc2[bb]);
            }
            float accf[8];
#pragma unroll
            for (int bb = 0; bb < 8; bb++) {
                float2 p = unpk(acc2[bb]);
                accf[bb] = p.x + p.y;
            }
            __syncwarp();
            float* co = bufQ + c * SQ + aa * 8;
            *(float4*)(co) = make_float4(accf[0], accf[1], accf[2], accf[3]);
            *(float4*)(co + 4) = make_float4(accf[4], accf[5], accf[6], accf[7]);
        }
    }
    __syncthreads();

    // ---- Phase 3a: LN partial sums over 128 channels ----
    {
        float s = 0.f, s2 = 0.f;
#pragma unroll 1
        for (int cb = 0; cb < 32; cb++) {
            float v = bufQ[(cb * 4 + lane) * SQ + pix];
            s += v;
            s2 += v * v;
        }
        psum[lane * 64 + pix] = s;
        psq[lane * 64 + pix] = s2;
    }
    __syncthreads();

    // ---- Phase 3b: normalize, gate by v (from global), write gatedT ----
    {
        float mu = (psum[pix] + psum[64 + pix] + psum[128 + pix] + psum[192 + pix]) *
                   (1.f / 128.f);
        float ex2 = (psq[pix] + psq[64 + pix] + psq[128 + pix] + psq[192 + pix]) *
                    (1.f / 128.f);
        float var = ex2 - mu * mu;
        float rstd = rsqrtf(var + 1e-5f);
        const float* vsrc = base + 256 * 64;
#pragma unroll 8
        for (int cb = 0; cb < 32; cb++) {
            int c = cb * 4 + lane;
            float vv = __ldg(vsrc + c * 64 + pix);
            float g = (bufQ[c * SQ + pix] - mu) * rstd * __ldg(lnw + c) + __ldg(lnb + c);
            gatedT[pix * 132 + c] = g * vv;
        }
    }
    __syncthreads();

    // ---- Phase 4: projection 128 -> 64, f32x2 reduction pairs ----
    {
        int o = t >> 2;       // 0..63
        int pl = t & 3;       // pixel interleave lane
        u64 acc2[16];
        const u64 z = splat2(0.f);
#pragma unroll
        for (int pp2 = 0; pp2 < 16; pp2++) acc2[pp2] = z;
        const ulonglong2* wrow = (const ulonglong2*)(w_out + o * 128);
#pragma unroll 1
        for (int cq = 0; cq < 32; cq++) {
            ulonglong2 w2 = __ldg(wrow + cq);
#pragma unroll
            for (int pp2 = 0; pp2 < 16; pp2++) {
                int p = pp2 * 4 + pl;
                ulonglong2 g2 = *(const ulonglong2*)(gatedT + p * 132 + cq * 4);
                acc2[pp2] = ffma2(w2.x, g2.x, acc2[pp2]);
                acc2[pp2] = ffma2(w2.y, g2.y, acc2[pp2]);
            }
        }
#pragma unroll
        for (int pp2 = 0; pp2 < 16; pp2++) {
            float2 r = unpk(acc2[pp2]);
            projbuf[o * 68 + pp2 * 4 + pl] = r.x + r.y;
        }
    }
    __syncthreads();

    // ---- Phase 5: coalesced writeout ----
    {
        int o2 = t >> 2;
        int part = t & 3;
        float* ob = out + ((long)(b * 64 + o2) * IMG + y0) * IMG + x0;
#pragma unroll
        for (int ry = 0; ry < 2; ry++) {
            int y = part * 2 + ry;
            float4 v0 = *(const float4*)(projbuf + o2 * 68 + y * 8);
            float4 v1 = *(const float4*)(projbuf + o2 * 68 + y * 8 + 4);
            *(float4*)(ob + y * IMG) = v0;
            *(float4*)(ob + y * IMG + 4) = v1;
        }
    }
}

// ---------------------------------------------------------------------------
extern "C" void kernel_launch(void* const* d_in, const int* in_sizes, int n_in,
                              void* d_out, int out_size) {
    const float* x = (const float*)d_in[0];
    const float* w1 = (const float*)d_in[1];
    const float* wdw = (const float*)d_in[2];
    const float* wout = (const float*)d_in[3];
    const float* lnw = (const float*)d_in[4];
    const float* lnb = (const float*)d_in[5];
    float* out = (float*)d_out;

    cudaFuncSetAttribute(conv1x1_kernel, cudaFuncAttributeMaxDynamicSharedMemorySize,
                         C1_SMEM_BYTES);
    cudaFuncSetAttribute(fsas2_kernel, cudaFuncAttributeMaxDynamicSharedMemorySize,
                         SMEM2_FLOATS * 4);

    conv1x1_kernel<<<dim3(2048, 3, 1), 256, C1_SMEM_BYTES>>>(x, w1);
    dw3x3_kernel<<<dim3(16, 384, 4), 256>>>(wdw);
    fsas2_kernel<<<4096, 256, SMEM2_FLOATS * 4>>>(wout, lnw, lnb, out);
}

// round 15
// speedup vs baseline: 1.3026x; 1.0940x over previous
#include <cuda_runtime.h>
#include <cuda_bf16.h>
#include <cstdint>

#define HW 65536
#define IMG 256

typedef unsigned long long u64;

static __device__ float g_hidden[(size_t)4 * 384 * HW];
static __device__ float g_qkv[(size_t)4 * 1024 * 384 * 64];

// ---------------- f32x2 helpers ----------------
__device__ __forceinline__ u64 ffma2(u64 a, u64 b, u64 c) {
    u64 d;
    asm("fma.rn.f32x2 %0, %1, %2, %3;" : "=l"(d) : "l"(a), "l"(b), "l"(c));
    return d;
}
__device__ __forceinline__ u64 splat2(float a) {
    u64 r;
    asm("mov.b64 %0, {%1, %1};" : "=l"(r) : "f"(a));
    return r;
}
__device__ __forceinline__ float2 unpk(u64 v) {
    float lo, hi;
    asm("mov.b64 {%0, %1}, %2;" : "=f"(lo), "=f"(hi) : "l"(v));
    return make_float2(lo, hi);
}

// ---------------- mma.sync helpers ----------------
// pack two floats to bf16x2: low half = lo, high half = hi
__device__ __forceinline__ uint32_t cvt_bf2(float lo, float hi) {
    uint32_t r;
    asm("cvt.rn.bf16x2.f32 %0, %1, %2;" : "=r"(r) : "f"(hi), "f"(lo));
    return r;
}
__device__ __forceinline__ void mma16816(float* c, const uint32_t* a, const uint32_t* b) {
    asm volatile(
        "mma.sync.aligned.m16n8k16.row.col.f32.bf16.bf16.f32 "
        "{%0,%1,%2,%3}, {%4,%5,%6,%7}, {%8,%9}, {%0,%1,%2,%3};"
        : "+f"(c[0]), "+f"(c[1]), "+f"(c[2]), "+f"(c[3])
        : "r"(a[0]), "r"(a[1]), "r"(a[2]), "r"(a[3]), "r"(b[0]), "r"(b[1]));
}

// ---------------------------------------------------------------------------
// Kernel 1: 1x1 conv 64->384 via mma.sync bf16 hi/lo split.
// CTA: 128 o x 128 px, K=64. smem fragment-packed operands:
//   A (w): [8 mtile][4 kstep][32 lane][4 reg] u32, hi @0, lo @16384
//   B (x): [16 ntile][4 kstep][32 lane][2 reg] u32, hi @32768, lo @49152
// total 65536 B. 8 warps: warp w -> o band (w>>1)*32, px band (w&1)*64.
// ---------------------------------------------------------------------------
#define C1M_SMEM 65536

__global__ __launch_bounds__(256) void conv1x1_mma(const float* __restrict__ x,
                                                   const float* __restrict__ w1) {
    extern __shared__ char smc[];
    uint32_t* Ah = (uint32_t*)smc;
    uint32_t* Al = (uint32_t*)(smc + 16384);
    uint32_t* Bh = (uint32_t*)(smc + 32768);
    uint32_t* Bl = (uint32_t*)(smc + 49152);
    const int t = threadIdx.x;
    const long px0 = (long)blockIdx.x * 128;
    const int b = (int)(px0 >> 16);
    const int hw0 = (int)(px0 & 65535);
    const int o0 = blockIdx.y * 128;

    // ---- A writer: w1[o0+o][2*k2..2*k2+1] -> fragment-packed hi/lo ----
    const float* wb = w1 + (long)o0 * 64;
#pragma unroll
    for (int i = 0; i < 16; i++) {
        int idx = t + i * 256;            // 4096 = 128 o x 32 k2
        int k2 = idx & 31, o = idx >> 5;
        float2 v = *(const float2*)(wb + o * 64 + k2 * 2);
        uint32_t hp = cvt_bf2(v.x, v.y);
        float h0 = __uint_as_float(hp << 16);
        float h1 = __uint_as_float(hp & 0xFFFF0000u);
        uint32_t lp = cvt_bf2(v.x - h0, v.y - h1);
        int k = k2 * 2;
        int kk = k & 15, kstep = k >> 4;
        int mtile = o >> 4, r = o & 15;
        int lane = (r & 7) * 4 + ((kk >> 1) & 3);
        int reg = (r >> 3) + 2 * (kk >> 3);
        int off = ((mtile * 4 + kstep) * 32 + lane) * 4 + reg;
        Ah[off] = hp;
        Al[off] = lp;
    }
    // ---- B writer: x[c..c+1][hw0+p] -> fragment-packed hi/lo ----
    const float* xb = x + (long)b * 64 * HW + hw0;
#pragma unroll
    for (int i = 0; i < 16; i++) {
        int idx = t + i * 256;            // 4096 = 32 k2 x 128 p
        int p = idx & 127, k2 = idx >> 7;
        int c = k2 * 2;
        float v0 = __ldg(xb + (long)c * HW + p);
        float v1 = __ldg(xb + (long)(c + 1) * HW + p);
        uint32_t hp = cvt_bf2(v0, v1);
        float h0 = __uint_as_float(hp << 16);
        float h1 = __uint_as_float(hp & 0xFFFF0000u);
        uint32_t lp = cvt_bf2(v0 - h0, v1 - h1);
        int kk = c & 15, kstep = k2 >> 3;
        int ntile = p >> 3, nn = p & 7;
        int lane = nn * 4 + ((kk >> 1) & 3);
        int reg = kk >> 3;
        int off = ((ntile * 4 + kstep) * 32 + lane) * 2 + reg;
        Bh[off] = hp;
        Bl[off] = lp;
    }
    __syncthreads();

    // ---- MMA mainloop: 3 products (AhBh, AhBl, AlBh) x 4 ksteps ----
    const int w = t >> 5, lane = t & 31;
    const int wm = w >> 1;    // 0..3 o band
    const int wn = w & 1;     // 0..1 px band
    float acc[2][8][4];
#pragma unroll
    for (int mi = 0; mi < 2; mi++)
#pragma unroll
        for (int ni = 0; ni < 8; ni++)
#pragma unroll
            for (int e = 0; e < 4; e++) acc[mi][ni][e] = 0.f;

#pragma unroll
    for (int prod = 0; prod < 3; prod++) {
        const uint32_t* Ause = (prod == 2) ? Al : Ah;
        const uint32_t* Buse = (prod == 1) ? Bl : Bh;
#pragma unroll
        for (int ks = 0; ks < 4; ks++) {
            uint32_t a0[4], a1[4];
            *(uint4*)a0 = *(const uint4*)&Ause[(((wm * 2 + 0) * 4 + ks) * 32 + lane) * 4];
            *(uint4*)a1 = *(const uint4*)&Ause[(((wm * 2 + 1) * 4 + ks) * 32 + lane) * 4];
#pragma unroll
            for (int ni = 0; ni < 8; ni++) {
                uint32_t bf[2];
                *(uint2*)bf = *(const uint2*)&Buse[(((wn * 8 + ni) * 4 + ks) * 32 + lane) * 2];
                mma16816(acc[0][ni], a0, bf);
                mma16816(acc[1][ni], a1, bf);
            }
        }
    }

    // ---- epilogue: direct stores, float2 pairs ----
    {
        int g = lane >> 2, tig = lane & 3;
        float* ghb = g_hidden + (long)b * 384 * HW + hw0;
#pragma unroll
        for (int mi = 0; mi < 2; mi++) {
            int o = o0 + wm * 32 + mi * 16 + g;
#pragma unroll
            for (int ni = 0; ni < 8; ni++) {
                int px = wn * 64 + ni * 8 + tig * 2;
                float* p0 = ghb + (long)o * HW + px;
                *(float2*)p0 = make_float2(acc[mi][ni][0], acc[mi][ni][1]);
                *(float2*)(p0 + (long)8 * HW) = make_float2(acc[mi][ni][2], acc[mi][ni][3]);
            }
        }
    }
}

// ---------------------------------------------------------------------------
// Kernel 2: depthwise 3x3 (unchanged), writes patched qkv layout.
// ---------------------------------------------------------------------------
__global__ __launch_bounds__(256) void dw3x3_kernel(const float* __restrict__ wdw) {
    __shared__ float smh[66 * 68];
    const int t = threadIdx.x;
    const int tix = blockIdx.x;
    const int ch = blockIdx.y;
    const int b = blockIdx.z;
    const int ty = tix >> 2, tx = tix & 3;
    const int y0 = ty * 64, x0 = tx * 64;

    const float* src = g_hidden + (long)(b * 384 + ch) * HW;
    for (int l = t; l < 66 * 66; l += 256) {
        int r = l / 66, c = l - r * 66;
        int y = y0 + r - 1, x = x0 + c - 1;
        float v = 0.f;
        if ((unsigned)y < 256u && (unsigned)x < 256u) v = src[y * IMG + x];
        smh[r * 68 + c] = v;
    }
    float w[9];
#pragma unroll
    for (int i = 0; i < 9; i++) w[i] = __ldg(wdw + ch * 9 + i);
    __syncthreads();

#pragma unroll 4
    for (int i = 0; i < 16; i++) {
        int L = t + i * 256;
        int p = L >> 6, inner = L & 63;
        int tpy = p >> 3, tpx = p & 7;
        int iy = inner >> 3, ix = inner & 7;
        int y = tpy * 8 + iy, x = tpx * 8 + ix;
        float acc = 0.f;
#pragma unroll
        for (int ky = 0; ky < 3; ky++)
#pragma unroll
            for (int kx = 0; kx < 3; kx++)
                acc += smh[(y + ky) * 68 + (x + kx)] * w[ky * 3 + kx];
        int pg = (ty * 8 + tpy) * 32 + (tx * 8 + tpx);
        g_qkv[((long)(b * 1024 + pg) * 384 + ch) * 64 + inner] = acc;
    }
}

// ---------------------------------------------------------------------------
// Kernel 3: per-patch attention (best variant: scalar phase 2, f32x2 phase 4)
// ---------------------------------------------------------------------------
#define SQ 68
#define S_BUFK 8704
#define S_PSUM 17920
#define S_PSQ 18176
#define SMEM2_FLOATS 18432

__global__ __launch_bounds__(256, 3) void fsas2_kernel(const float* __restrict__ w_out,
                                                       const float* __restrict__ lnw,
                                                       const float* __restrict__ lnb,
                                                       float* __restrict__ out) {
    extern __shared__ float sm[];
    float* bufQ = sm;
    float* bufK = sm + S_BUFK;
    float* gatedT = bufK;
    float* projbuf = sm;
    float* psum = sm + S_PSUM;
    float* psq = sm + S_PSQ;

    const int t = threadIdx.x;
    const int pid = blockIdx.x;
    const int b = pid >> 10;
    const int patch = pid & 1023;
    const int ph = patch >> 5;
    const int pw = patch & 31;
    const int y0 = ph * 8, x0 = pw * 8;
    const int lane = t >> 6;
    const int pix = t & 63;

    const float* base = g_qkv + (long)pid * 384 * 64;

#pragma unroll
    for (int r = 0; r < 8; r++) {
        int idx = t + r * 256;
        float4 v = ((const float4*)base)[idx];
        int c = idx >> 4;
        int word = (idx & 15) * 4;
        *(float4*)(bufQ + c * SQ + word) = v;
    }
#pragma unroll
    for (int r = 0; r < 8; r++) {
        int idx = t + r * 256;
        float4 v = ((const float4*)(base + 8192))[idx];
        int c = idx >> 4;
        int word = (idx & 15) * 4;
        int row = word >> 3, col = word & 7;
        float* dk = bufK + c * 72 + row * 9 + col;
        dk[0] = v.x; dk[1] = v.y; dk[2] = v.z; dk[3] = v.w;
    }
    __syncthreads();

    {
        const int w = t >> 5;
        const int ln = t & 31;
        const int aa = ln & 7;
        const int csub = ln >> 3;
#pragma unroll 1
        for (int r = 0; r < 4; r++) {
            int c = w * 16 + r * 4 + csub;
            const float* bq = bufQ + c * SQ;
            const float* bk = bufK + c * 72;
            float acc[8];
#pragma unroll
            for (int bb = 0; bb < 8; bb++) acc[bb] = 0.f;
#pragma unroll
            for (int i = 0; i < 8; i++) {
                float4 q0 = *(const float4*)(bq + i * 8);
                float4 q1 = *(const float4*)(bq + i * 8 + 4);
                float qr[8] = {q0.x, q0.y, q0.z, q0.w, q1.x, q1.y, q1.z, q1.w};
                int ka = (aa - i) & 7;
                const float* kr = bk + ka * 9;
                float kk[8];
#pragma unroll
                for (int m = 0; m < 8; m++) kk[m] = kr[m];
#pragma unroll
                for (int j = 0; j < 8; j++)
#pragma unroll
                    for (int bb = 0; bb < 8; bb++) acc[bb] += qr[j] * kk[(bb - j) & 7];
            }
            __syncwarp();
            float* co = bufQ + c * SQ + aa * 8;
            *(float4*)(co) = make_float4(acc[0], acc[1], acc[2], acc[3]);
            *(float4*)(co + 4) = make_float4(acc[4], acc[5], acc[6], acc[7]);
        }
    }
    __syncthreads();

    {
        float s = 0.f, s2 = 0.f;
#pragma unroll 1
        for (int cb = 0; cb < 32; cb++) {
            float v = bufQ[(cb * 4 + lane) * SQ + pix];
            s += v;
            s2 += v * v;
        }
        psum[lane * 64 + pix] = s;
        psq[lane * 64 + pix] = s2;
    }
    __syncthreads();

    {
        float mu = (psum[pix] + psum[64 + pix] + psum[128 + pix] + psum[192 + pix]) *
                   (1.f / 128.f);
        float ex2 = (psq[pix] + psq[64 + pix] + psq[128 + pix] + psq[192 + pix]) *
                    (1.f / 128.f);
        float var = ex2 - mu * mu;
        float rstd = rsqrtf(var + 1e-5f);
        const float* vsrc = base + 256 * 64;
#pragma unroll 8
        for (int cb = 0; cb < 32; cb++) {
            int c = cb * 4 + lane;
            float vv = __ldg(vsrc + c * 64 + pix);
            float g = (bufQ[c * SQ + pix] - mu) * rstd * __ldg(lnw + c) + __ldg(lnb + c);
            gatedT[pix * 132 + c] = g * vv;
        }
    }
    __syncthreads();

    {
        int o = t >> 2;
        int pl = t & 3;
        u64 acc2[16];
        const u64 z = splat2(0.f);
#pragma unroll
        for (int pp2 = 0; pp2 < 16; pp2++) acc2[pp2] = z;
        const ulonglong2* wrow = (const ulonglong2*)(w_out + o * 128);
#pragma unroll 1
        for (int cq = 0; cq < 32; cq++) {
            ulonglong2 w2 = __ldg(wrow + cq);
#pragma unroll
            for (int pp2 = 0; pp2 < 16; pp2++) {
                int p = pp2 * 4 + pl;
                ulonglong2 g2 = *(const ulonglong2*)(gatedT + p * 132 + cq * 4);
                acc2[pp2] = ffma2(w2.x, g2.x, acc2[pp2]);
                acc2[pp2] = ffma2(w2.y, g2.y, acc2[pp2]);
            }
        }
#pragma unroll
        for (int pp2 = 0; pp2 < 16; pp2++) {
            float2 r = unpk(acc2[pp2]);
            projbuf[o * 68 + pp2 * 4 + pl] = r.x + r.y;
        }
    }
    __syncthreads();

    {
        int o2 = t >> 2;
        int part = t & 3;
        float* ob = out + ((long)(b * 64 + o2) * IMG + y0) * IMG + x0;
#pragma unroll
        for (int ry = 0; ry < 2; ry++) {
            int y = part * 2 + ry;
            float4 v0 = *(const float4*)(projbuf + o2 * 68 + y * 8);
            float4 v1 = *(const float4*)(projbuf + o2 * 68 + y * 8 + 4);
            *(float4*)(ob + y * IMG) = v0;
            *(float4*)(ob + y * IMG + 4) = v1;
        }
    }
}

// ---------------------------------------------------------------------------
extern "C" void kernel_launch(void* const* d_in, const int* in_sizes, int n_in,
                              void* d_out, int out_size) {
    const float* x = (const float*)d_in[0];
    const float* w1 = (const float*)d_in[1];
    const float* wdw = (const float*)d_in[2];
    const float* wout = (const float*)d_in[3];
    const float* lnw = (const float*)d_in[4];
    const float* lnb = (const float*)d_in[5];
    float* out = (float*)d_out;

    cudaFuncSetAttribute(conv1x1_mma, cudaFuncAttributeMaxDynamicSharedMemorySize, C1M_SMEM);
    cudaFuncSetAttribute(fsas2_kernel, cudaFuncAttributeMaxDynamicSharedMemorySize,
                         SMEM2_FLOATS * 4);

    conv1x1_mma<<<dim3(2048, 3, 1), 256, C1M_SMEM>>>(x, w1);
    dw3x3_kernel<<<dim3(16, 384, 4), 256>>>(wdw);
    fsas2_kernel<<<4096, 256, SMEM2_FLOATS * 4>>>(wout, lnw, lnb, out);
}

// round 16
// speedup vs baseline: 1.6641x; 1.2775x over previous
#include <cuda_runtime.h>
#include <cuda_bf16.h>
#include <cstdint>

#define HW 65536
#define IMG 256

typedef unsigned long long u64;

static __device__ float g_hidden[(size_t)4 * 384 * HW];
static __device__ float g_qkv[(size_t)4 * 1024 * 384 * 64];

// ---------------- mma.sync helpers ----------------
__device__ __forceinline__ uint32_t cvt_bf2(float lo, float hi) {
    uint32_t r;
    asm("cvt.rn.bf16x2.f32 %0, %1, %2;" : "=r"(r) : "f"(hi), "f"(lo));
    return r;
}
__device__ __forceinline__ void mma16816(float* c, const uint32_t* a, const uint32_t* b) {
    asm volatile(
        "mma.sync.aligned.m16n8k16.row.col.f32.bf16.bf16.f32 "
        "{%0,%1,%2,%3}, {%4,%5,%6,%7}, {%8,%9}, {%0,%1,%2,%3};"
        : "+f"(c[0]), "+f"(c[1]), "+f"(c[2]), "+f"(c[3])
        : "r"(a[0]), "r"(a[1]), "r"(a[2]), "r"(a[3]), "r"(b[0]), "r"(b[1]));
}

// ---------------------------------------------------------------------------
// Kernel 1: 1x1 conv 64->384 via mma.sync bf16 hi/lo split. 2 CTAs/SM.
// ---------------------------------------------------------------------------
#define C1M_SMEM 65536

__global__ __launch_bounds__(256, 2) void conv1x1_mma(const float* __restrict__ x,
                                                      const float* __restrict__ w1) {
    extern __shared__ char smc[];
    uint32_t* Ah = (uint32_t*)smc;
    uint32_t* Al = (uint32_t*)(smc + 16384);
    uint32_t* Bh = (uint32_t*)(smc + 32768);
    uint32_t* Bl = (uint32_t*)(smc + 49152);
    const int t = threadIdx.x;
    const long px0 = (long)blockIdx.x * 128;
    const int b = (int)(px0 >> 16);
    const int hw0 = (int)(px0 & 65535);
    const int o0 = blockIdx.y * 128;

    // ---- A writer: w1 fragments hi/lo ----
    const float* wb = w1 + (long)o0 * 64;
#pragma unroll
    for (int i = 0; i < 16; i++) {
        int idx = t + i * 256;            // 4096 = 128 o x 32 k2
        int k2 = idx & 31, o = idx >> 5;
        float2 v = *(const float2*)(wb + o * 64 + k2 * 2);
        uint32_t hp = cvt_bf2(v.x, v.y);
        float h0 = __uint_as_float(hp << 16);
        float h1 = __uint_as_float(hp & 0xFFFF0000u);
        uint32_t lp = cvt_bf2(v.x - h0, v.y - h1);
        int k = k2 * 2;
        int kk = k & 15, kstep = k >> 4;
        int mtile = o >> 4, r = o & 15;
        int lane = (r & 7) * 4 + ((kk >> 1) & 3);
        int reg = (r >> 3) + 2 * (kk >> 3);
        int off = ((mtile * 4 + kstep) * 32 + lane) * 4 + reg;
        Ah[off] = hp;
        Al[off] = lp;
    }
    // ---- B writer: x fragments hi/lo ----
    const float* xb = x + (long)b * 64 * HW + hw0;
#pragma unroll
    for (int i = 0; i < 16; i++) {
        int idx = t + i * 256;            // 4096 = 32 k2 x 128 p
        int p = idx & 127, k2 = idx >> 7;
        int c = k2 * 2;
        float v0 = __ldg(xb + (long)c * HW + p);
        float v1 = __ldg(xb + (long)(c + 1) * HW + p);
        uint32_t hp = cvt_bf2(v0, v1);
        float h0 = __uint_as_float(hp << 16);
        float h1 = __uint_as_float(hp & 0xFFFF0000u);
        uint32_t lp = cvt_bf2(v0 - h0, v1 - h1);
        int kk = c & 15, kstep = k2 >> 3;
        int ntile = p >> 3, nn = p & 7;
        int lane = nn * 4 + ((kk >> 1) & 3);
        int reg = kk >> 3;
        int off = ((ntile * 4 + kstep) * 32 + lane) * 2 + reg;
        Bh[off] = hp;
        Bl[off] = lp;
    }
    __syncthreads();

    const int w = t >> 5, lane = t & 31;
    const int wm = w >> 1;    // 0..3 o band
    const int wn = w & 1;     // 0..1 px band
    float acc[2][8][4];
#pragma unroll
    for (int mi = 0; mi < 2; mi++)
#pragma unroll
        for (int ni = 0; ni < 8; ni++)
#pragma unroll
            for (int e = 0; e < 4; e++) acc[mi][ni][e] = 0.f;

#pragma unroll
    for (int prod = 0; prod < 3; prod++) {
        const uint32_t* Ause = (prod == 2) ? Al : Ah;
        const uint32_t* Buse = (prod == 1) ? Bl : Bh;
#pragma unroll
        for (int ks = 0; ks < 4; ks++) {
            uint32_t a0[4], a1[4];
            *(uint4*)a0 = *(const uint4*)&Ause[(((wm * 2 + 0) * 4 + ks) * 32 + lane) * 4];
            *(uint4*)a1 = *(const uint4*)&Ause[(((wm * 2 + 1) * 4 + ks) * 32 + lane) * 4];
#pragma unroll
            for (int ni = 0; ni < 8; ni++) {
                uint32_t bf[2];
                *(uint2*)bf = *(const uint2*)&Buse[(((wn * 8 + ni) * 4 + ks) * 32 + lane) * 2];
                mma16816(acc[0][ni], a0, bf);
                mma16816(acc[1][ni], a1, bf);
            }
        }
    }

    {
        int g = lane >> 2, tig = lane & 3;
        float* ghb = g_hidden + (long)b * 384 * HW + hw0;
#pragma unroll
        for (int mi = 0; mi < 2; mi++) {
            int o = o0 + wm * 32 + mi * 16 + g;
#pragma unroll
            for (int ni = 0; ni < 8; ni++) {
                int px = wn * 64 + ni * 8 + tig * 2;
                float* p0 = ghb + (long)o * HW + px;
                *(float2*)p0 = make_float2(acc[mi][ni][0], acc[mi][ni][1]);
                *(float2*)(p0 + (long)8 * HW) = make_float2(acc[mi][ni][2], acc[mi][ni][3]);
            }
        }
    }
}

// ---------------------------------------------------------------------------
// Kernel 2: depthwise 3x3 (unchanged), writes patched qkv layout.
// ---------------------------------------------------------------------------
__global__ __launch_bounds__(256) void dw3x3_kernel(const float* __restrict__ wdw) {
    __shared__ float smh[66 * 68];
    const int t = threadIdx.x;
    const int tix = blockIdx.x;
    const int ch = blockIdx.y;
    const int b = blockIdx.z;
    const int ty = tix >> 2, tx = tix & 3;
    const int y0 = ty * 64, x0 = tx * 64;

    const float* src = g_hidden + (long)(b * 384 + ch) * HW;
    for (int l = t; l < 66 * 66; l += 256) {
        int r = l / 66, c = l - r * 66;
        int y = y0 + r - 1, x = x0 + c - 1;
        float v = 0.f;
        if ((unsigned)y < 256u && (unsigned)x < 256u) v = src[y * IMG + x];
        smh[r * 68 + c] = v;
    }
    float w[9];
#pragma unroll
    for (int i = 0; i < 9; i++) w[i] = __ldg(wdw + ch * 9 + i);
    __syncthreads();

#pragma unroll 4
    for (int i = 0; i < 16; i++) {
        int L = t + i * 256;
        int p = L >> 6, inner = L & 63;
        int tpy = p >> 3, tpx = p & 7;
        int iy = inner >> 3, ix = inner & 7;
        int y = tpy * 8 + iy, x = tpx * 8 + ix;
        float acc = 0.f;
#pragma unroll
        for (int ky = 0; ky < 3; ky++)
#pragma unroll
            for (int kx = 0; kx < 3; kx++)
                acc += smh[(y + ky) * 68 + (x + kx)] * w[ky * 3 + kx];
        int pg = (ty * 8 + tpy) * 32 + (tx * 8 + tpx);
        g_qkv[((long)(b * 1024 + pg) * 384 + ch) * 64 + inner] = acc;
    }
}

// ---------------------------------------------------------------------------
// Kernel 3: per-patch attention. Phases 1-3a unchanged (proven).
// Phase 3b: LN + gate -> bf16 hi/lo B-fragments (overlay bufK).
// Then w_out -> bf16 hi/lo A-fragments (overlay bufQ, dead).
// Phase 4: mma.sync M=64o N=64px K=128c, direct global store.
//   bufQ @0      [128][68] fl (8704)  | later Ah @0 (4096 u32), Al @4096
//   bufK @8704   [128][72] fl (9216)  | later Bh @8704fl (4096 u32), Bl +4096
//   psum @17920, psq @18176 [4][64]
// total 18432 fl = 73728 B -> 3 CTAs/SM
// ---------------------------------------------------------------------------
#define SQ 68
#define S_BUFK 8704
#define S_PSUM 17920
#define S_PSQ 18176
#define SMEM2_FLOATS 18432

__global__ __launch_bounds__(256, 3) void fsas2_kernel(const float* __restrict__ w_out,
                                                       const float* __restrict__ lnw,
                                                       const float* __restrict__ lnb,
                                                       float* __restrict__ out) {
    extern __shared__ float sm[];
    float* bufQ = sm;
    float* bufK = sm + S_BUFK;
    float* psum = sm + S_PSUM;
    float* psq = sm + S_PSQ;
    uint32_t* Ah = (uint32_t*)sm;                 // phase-4 overlays
    uint32_t* Al = Ah + 4096;
    uint32_t* Bh = (uint32_t*)(sm + S_BUFK);
    uint32_t* Bl = Bh + 4096;

    const int t = threadIdx.x;
    const int pid = blockIdx.x;
    const int b = pid >> 10;
    const int patch = pid & 1023;
    const int ph = patch >> 5;
    const int pw = patch & 31;
    const int y0 = ph * 8, x0 = pw * 8;
    const int lane4 = t >> 6;      // 0..3
    const int pix = t & 63;

    const float* base = g_qkv + (long)pid * 384 * 64;

    // ---- Phase 1: load q (stride-68 rows) and k (stride-9 rows) ----
#pragma unroll
    for (int r = 0; r < 8; r++) {
        int idx = t + r * 256;
        float4 v = ((const float4*)base)[idx];
        int c = idx >> 4;
        int word = (idx & 15) * 4;
        *(float4*)(bufQ + c * SQ + word) = v;
    }
#pragma unroll
    for (int r = 0; r < 8; r++) {
        int idx = t + r * 256;
        float4 v = ((const float4*)(base + 8192))[idx];
        int c = idx >> 4;
        int word = (idx & 15) * 4;
        int row = word >> 3, col = word & 7;
        float* dk = bufK + c * 72 + row * 9 + col;
        dk[0] = v.x; dk[1] = v.y; dk[2] = v.z; dk[3] = v.w;
    }
    __syncthreads();

    // ---- Phase 2: 8x8 circular conv; warp owns 16-ch band; in place ----
    {
        const int w = t >> 5;
        const int ln = t & 31;
        const int aa = ln & 7;
        const int csub = ln >> 3;
#pragma unroll 1
        for (int r = 0; r < 4; r++) {
            int c = w * 16 + r * 4 + csub;
            const float* bq = bufQ + c * SQ;
            const float* bk = bufK + c * 72;
            float acc[8];
#pragma unroll
            for (int bb = 0; bb < 8; bb++) acc[bb] = 0.f;
#pragma unroll
            for (int i = 0; i < 8; i++) {
                float4 q0 = *(const float4*)(bq + i * 8);
                float4 q1 = *(const float4*)(bq + i * 8 + 4);
                float qr[8] = {q0.x, q0.y, q0.z, q0.w, q1.x, q1.y, q1.z, q1.w};
                int ka = (aa - i) & 7;
                const float* kr = bk + ka * 9;
                float kk[8];
#pragma unroll
                for (int m = 0; m < 8; m++) kk[m] = kr[m];
#pragma unroll
                for (int j = 0; j < 8; j++)
#pragma unroll
                    for (int bb = 0; bb < 8; bb++) acc[bb] += qr[j] * kk[(bb - j) & 7];
            }
            __syncwarp();
            float* co = bufQ + c * SQ + aa * 8;
            *(float4*)(co) = make_float4(acc[0], acc[1], acc[2], acc[3]);
            *(float4*)(co + 4) = make_float4(acc[4], acc[5], acc[6], acc[7]);
        }
    }
    __syncthreads();

    // ---- Phase 3a: LN partial sums over 128 channels ----
    {
        float s = 0.f, s2 = 0.f;
#pragma unroll 1
        for (int cb = 0; cb < 32; cb++) {
            float v = bufQ[(cb * 4 + lane4) * SQ + pix];
            s += v;
            s2 += v * v;
        }
        psum[lane4 * 64 + pix] = s;
        psq[lane4 * 64 + pix] = s2;
    }
    __syncthreads();

    // ---- Phase 3b: normalize + gate, write bf16 hi/lo B-fragments ----
    {
        float mu = (psum[pix] + psum[64 + pix] + psum[128 + pix] + psum[192 + pix]) *
                   (1.f / 128.f);
        float ex2 = (psq[pix] + psq[64 + pix] + psq[128 + pix] + psq[192 + pix]) *
                    (1.f / 128.f);
        float rstd = rsqrtf(ex2 - mu * mu + 1e-5f);
        const float* vsrc = base + 256 * 64;
        const int cpair = t >> 6;                 // 0..3
        const int ntile = pix >> 3, nn = pix & 7;
#pragma unroll 4
        for (int m = 0; m < 16; m++) {
            int c0 = m * 8 + cpair * 2;
            int c1 = c0 + 1;
            float g0 = (bufQ[c0 * SQ + pix] - mu) * rstd * __ldg(lnw + c0) + __ldg(lnb + c0);
            float g1 = (bufQ[c1 * SQ + pix] - mu) * rstd * __ldg(lnw + c1) + __ldg(lnb + c1);
            g0 *= __ldg(vsrc + c0 * 64 + pix);
            g1 *= __ldg(vsrc + c1 * 64 + pix);
            uint32_t hp = cvt_bf2(g0, g1);
            float h0 = __uint_as_float(hp << 16);
            float h1 = __uint_as_float(hp & 0xFFFF0000u);
            uint32_t lp = cvt_bf2(g0 - h0, g1 - h1);
            int kk = c0 & 15, kstep = c0 >> 4;
            int lf = nn * 4 + ((kk >> 1) & 3);
            int reg = kk >> 3;
            int off = ((ntile * 8 + kstep) * 32 + lf) * 2 + reg;
            Bh[off] = hp;
            Bl[off] = lp;
        }
    }
    __syncthreads();          // bufQ now dead

    // ---- w_out -> A fragments hi/lo (into bufQ region) ----
#pragma unroll 4
    for (int i = 0; i < 16; i++) {
        int idx = t + i * 256;            // 4096 = 64 o x 64 k2
        int k2 = idx & 63, o = idx >> 6;
        float2 v = *(const float2*)(w_out + o * 128 + k2 * 2);
        uint32_t hp = cvt_bf2(v.x, v.y);
        float h0 = __uint_as_float(hp << 16);
        float h1 = __uint_as_float(hp & 0xFFFF0000u);
        uint32_t lp = cvt_bf2(v.x - h0, v.y - h1);
        int k = k2 * 2;
        int kk = k & 15, kstep = k >> 4;
        int mtile = o >> 4, r = o & 15;
        int lf = (r & 7) * 4 + ((kk >> 1) & 3);
        int reg = (r >> 3) + 2 * (kk >> 3);
        int off = ((mtile * 8 + kstep) * 32 + lf) * 4 + reg;
        Ah[off] = hp;
        Al[off] = lp;
    }
    __syncthreads();

    // ---- Phase 4: mma projection, direct store ----
    {
        const int w = t >> 5, lane = t & 31;
        const int mtile = w >> 1;     // 0..3 (16 o each)
        const int nhalf = w & 1;      // 32 px each
        float acc[4][4];
#pragma unroll
        for (int ni = 0; ni < 4; ni++)
#pragma unroll
            for (int e = 0; e < 4; e++) acc[ni][e] = 0.f;

#pragma unroll
        for (int prod = 0; prod < 3; prod++) {
            const uint32_t* Ause = (prod == 2) ? Al : Ah;
            const uint32_t* Buse = (prod == 1) ? Bl : Bh;
#pragma unroll
            for (int ks = 0; ks < 8; ks++) {
                uint32_t a[4];
                *(uint4*)a = *(const uint4*)&Ause[((mtile * 8 + ks) * 32 + lane) * 4];
#pragma unroll
                for (int ni = 0; ni < 4; ni++) {
                    uint32_t bf[2];
                    *(uint2*)bf =
                        *(const uint2*)&Buse[(((nhalf * 4 + ni) * 8 + ks) * 32 + lane) * 2];
                    mma16816(acc[ni], a, bf);
                }
            }
        }

        int g = lane >> 2, tig = lane & 3;
#pragma unroll
        for (int ni = 0; ni < 4; ni++) {
            int px = nhalf * 32 + ni * 8 + tig * 2;
            int pa = px >> 3, pb = px & 7;
            int olo = mtile * 16 + g;
            float* p0 = out + ((long)(b * 64 + olo) * IMG + y0 + pa) * IMG + x0 + pb;
            *(float2*)p0 = make_float2(acc[ni][0], acc[ni][1]);
            float* p1 = out + ((long)(b * 64 + olo + 8) * IMG + y0 + pa) * IMG + x0 + pb;
            *(float2*)p1 = make_float2(acc[ni][2], acc[ni][3]);
        }
    }
}

// ---------------------------------------------------------------------------
extern "C" void kernel_launch(void* const* d_in, const int* in_sizes, int n_in,
                              void* d_out, int out_size) {
    const float* x = (const float*)d_in[0];
    const float* w1 = (const float*)d_in[1];
    const float* wdw = (const float*)d_in[2];
    const float* wout = (const float*)d_in[3];
    const float* lnw = (const float*)d_in[4];
    const float* lnb = (const float*)d_in[5];
    float* out = (float*)d_out;

    cudaFuncSetAttribute(conv1x1_mma, cudaFuncAttributeMaxDynamicSharedMemorySize, C1M_SMEM);
    cudaFuncSetAttribute(fsas2_kernel, cudaFuncAttributeMaxDynamicSharedMemorySize,
                         SMEM2_FLOATS * 4);

    conv1x1_mma<<<dim3(2048, 3, 1), 256, C1M_SMEM>>>(x, w1);
    dw3x3_kernel<<<dim3(16, 384, 4), 256>>>(wdw);
    fsas2_kernel<<<4096, 256, SMEM2_FLOATS * 4>>>(wout, lnw, lnb, out);
}